// round 4
// baseline (speedup 1.0000x reference)
#include <cuda_runtime.h>
#include <cstdint>

#define TOK_N 131072   // B*T = 64*2048
#define DD    256      // D = V = 256
#define TT    2048

constexpr int BM = 64, BN = 64, BK = 32;

// Scratch (device globals: allocation-free rule)
__device__ float g_wx  [TOK_N * DD];   // 128 MB
__device__ float g_gate[TOK_N * DD];   // 128 MB
__device__ float g_ys  [TOK_N * DD];   // 128 MB

// packed f32x2 FMA (Blackwell-only; ptxas never auto-fuses this)
#define FMA2(d, a, b, c) \
    asm("fma.rn.f32x2 %0, %1, %2, %3;" : "=l"(d) : "l"(a), "l"(b), "l"(c))

__device__ __forceinline__ uint32_t smem_u32(const void* p) {
    uint32_t a;
    asm("{ .reg .u64 t; cvta.to.shared.u64 t, %1; cvt.u32.u64 %0, t; }"
        : "=r"(a) : "l"(p));
    return a;
}

// ---------------------------------------------------------------------------
// Kernel 1: fused embed-gather + dual projection (unchanged from R3 baseline)
// ---------------------------------------------------------------------------
__global__ __launch_bounds__(256) void proj_kernel(
    const int*   __restrict__ tokens,
    const float* __restrict__ E,
    const float* __restrict__ Wx,
    const float* __restrict__ Wz)
{
    __shared__ float As[BK][BM + 4];
    __shared__ float Bx[BK][BN + 4];
    __shared__ float Bz[BK][BN + 4];

    const int tid = threadIdx.x;
    const int m0  = blockIdx.x * BM;
    const int n0  = blockIdx.y * BN;

    const int lrow = tid >> 3;
    const int lk4  = tid & 7;

    const int tok0 = tokens[m0 + lrow];
    const int tok1 = tokens[m0 + lrow + 32];

    const int tr = (tid >> 4) << 2;
    const int tc = (tid & 15) << 2;

    float ax[4][4], az[4][4];
#pragma unroll
    for (int i = 0; i < 4; i++)
#pragma unroll
        for (int j = 0; j < 4; j++) { ax[i][j] = 0.f; az[i][j] = 0.f; }

    for (int k0 = 0; k0 < DD; k0 += BK) {
        float4 va0  = *(const float4*)&E [tok0 * DD        + k0 + lk4 * 4];
        float4 va1  = *(const float4*)&E [tok1 * DD        + k0 + lk4 * 4];
        float4 vbx0 = *(const float4*)&Wx[(n0 + lrow)      * DD + k0 + lk4 * 4];
        float4 vbx1 = *(const float4*)&Wx[(n0 + lrow + 32) * DD + k0 + lk4 * 4];
        float4 vbz0 = *(const float4*)&Wz[(n0 + lrow)      * DD + k0 + lk4 * 4];
        float4 vbz1 = *(const float4*)&Wz[(n0 + lrow + 32) * DD + k0 + lk4 * 4];

        __syncthreads();

        As[lk4*4+0][lrow]      = va0.x;  As[lk4*4+1][lrow]      = va0.y;
        As[lk4*4+2][lrow]      = va0.z;  As[lk4*4+3][lrow]      = va0.w;
        As[lk4*4+0][lrow + 32] = va1.x;  As[lk4*4+1][lrow + 32] = va1.y;
        As[lk4*4+2][lrow + 32] = va1.z;  As[lk4*4+3][lrow + 32] = va1.w;

        Bx[lk4*4+0][lrow]      = vbx0.x; Bx[lk4*4+1][lrow]      = vbx0.y;
        Bx[lk4*4+2][lrow]      = vbx0.z; Bx[lk4*4+3][lrow]      = vbx0.w;
        Bx[lk4*4+0][lrow + 32] = vbx1.x; Bx[lk4*4+1][lrow + 32] = vbx1.y;
        Bx[lk4*4+2][lrow + 32] = vbx1.z; Bx[lk4*4+3][lrow + 32] = vbx1.w;

        Bz[lk4*4+0][lrow]      = vbz0.x; Bz[lk4*4+1][lrow]      = vbz0.y;
        Bz[lk4*4+2][lrow]      = vbz0.z; Bz[lk4*4+3][lrow]      = vbz0.w;
        Bz[lk4*4+0][lrow + 32] = vbz1.x; Bz[lk4*4+1][lrow + 32] = vbz1.y;
        Bz[lk4*4+2][lrow + 32] = vbz1.z; Bz[lk4*4+3][lrow + 32] = vbz1.w;

        __syncthreads();

#pragma unroll
        for (int kk = 0; kk < BK; kk++) {
            float4 a  = *(const float4*)&As[kk][tr];
            float4 bx = *(const float4*)&Bx[kk][tc];
            float4 bz = *(const float4*)&Bz[kk][tc];
            const float av[4]  = {a.x, a.y, a.z, a.w};
            const float bxv[4] = {bx.x, bx.y, bx.z, bx.w};
            const float bzv[4] = {bz.x, bz.y, bz.z, bz.w};
#pragma unroll
            for (int i = 0; i < 4; i++)
#pragma unroll
                for (int j = 0; j < 4; j++) {
                    ax[i][j] = fmaf(av[i], bxv[j], ax[i][j]);
                    az[i][j] = fmaf(av[i], bzv[j], az[i][j]);
                }
        }
    }

#pragma unroll
    for (int i = 0; i < 4; i++) {
        float4 ox = make_float4(ax[i][0], ax[i][1], ax[i][2], ax[i][3]);
        *(float4*)&g_wx[(m0 + tr + i) * DD + n0 + tc] = ox;
        float4 oz;
        oz.x = 1.f / (1.f + __expf(-az[i][0]));
        oz.y = 1.f / (1.f + __expf(-az[i][1]));
        oz.z = 1.f / (1.f + __expf(-az[i][2]));
        oz.w = 1.f / (1.f + __expf(-az[i][3]));
        *(float4*)&g_gate[(m0 + tr + i) * DD + n0 + tc] = oz;
    }
}

// ---------------------------------------------------------------------------
// Kernel 2: Elman recurrence, v2.
//  - 2-CTA cluster per batch row; Wh half in registers as packed f32x2.
//  - thread = (4 outputs) x (32-k segment); conflict-free rotated LDS.128.
//  - shfl_xor cross-segment reduction (no __syncthreads).
//  - mbarrier step sync (256 local + 32 remote writer arrivals = 288),
//    triple-buffered h (2-phase reuse distance tolerates 1-phase borrow).
// ---------------------------------------------------------------------------
__global__ void __cluster_dims__(2, 1, 1) __launch_bounds__(256, 1)
rnn_kernel(const float* __restrict__ Wh)
{
    __shared__ __align__(16) float h_s[3][DD];
    __shared__ __align__(8) unsigned long long mbar;

    const int tid  = threadIdx.x;
    const int warp = tid >> 5;
    const int lane = tid & 31;
    const int s    = lane >> 2;          // k segment 0..7
    const int osub = lane & 3;
    const int b    = blockIdx.x >> 1;
    const int half = blockIdx.x & 1;     // cluster rank
    const int eL   = warp * 16 + osub * 4;   // local output base (4 outputs)
    const int eg   = half * 128 + eL;        // global output base
    const int k0   = s * 32;

    // weights: 4 rows x 32 k, packed as f32x2 (128 regs)
    unsigned long long wp[4][16];
#pragma unroll
    for (int o = 0; o < 4; o++) {
        const unsigned long long* wrow =
            (const unsigned long long*)(Wh + (size_t)(eg + o) * DD + k0);
#pragma unroll
        for (int j = 0; j < 16; j++) wp[o][j] = wrow[j];
    }

    h_s[0][tid] = 0.f;

    const uint32_t mbar_a = smem_u32(&mbar);
    const uint32_t h_a    = smem_u32(&h_s[0][0]);
    uint32_t mbar_peer, h_peer;
    asm("mapa.shared::cluster.u32 %0, %1, %2;" : "=r"(mbar_peer) : "r"(mbar_a), "r"(half ^ 1));
    asm("mapa.shared::cluster.u32 %0, %1, %2;" : "=r"(h_peer)    : "r"(h_a),    "r"(half ^ 1));

    if (tid == 0) {
        asm volatile("mbarrier.init.shared.b64 [%0], %1;" :: "r"(mbar_a), "r"(288) : "memory");
    }
    // one-time: make zero-init + mbar init visible cluster-wide
    asm volatile("barrier.cluster.arrive.aligned;" ::: "memory");
    asm volatile("barrier.cluster.wait.aligned;"   ::: "memory");

    const float* wx_p = g_wx   + (size_t)b * TT * DD;
    const float* gt_p = g_gate + (size_t)b * TT * DD;
    float*       y_p  = g_ys   + (size_t)b * TT * DD;

    const bool writer = (s == 0);
    float4 wx_c, gt_c, wx_n, gt_n;
    if (writer) {
        wx_c = *(const float4*)&wx_p[eg];
        gt_c = *(const float4*)&gt_p[eg];
    }

    int rbuf = 0;
    for (int t = 0; t < TT; t++) {
        int wbuf = rbuf + 1; if (wbuf == 3) wbuf = 0;

        // prefetch next step's inputs (full step of latency cover)
        if (writer && t + 1 < TT) {
            wx_n = *(const float4*)&wx_p[(t + 1) * DD + eg];
            gt_n = *(const float4*)&gt_p[(t + 1) * DD + eg];
        }

        // 4 outputs x my 32-k segment, rotated conflict-free smem reads
        const ulonglong2* hp = (const ulonglong2*)&h_s[rbuf][k0];
        unsigned long long acc0 = 0, acc1 = 0, acc2 = 0, acc3 = 0;
#pragma unroll
        for (int i = 0; i < 8; i++) {
            const int q = (i + s) & 7;
            ulonglong2 hv = hp[q];
            FMA2(acc0, wp[0][2*q],   hv.x, acc0);
            FMA2(acc1, wp[1][2*q],   hv.x, acc1);
            FMA2(acc2, wp[2][2*q],   hv.x, acc2);
            FMA2(acc3, wp[3][2*q],   hv.x, acc3);
            FMA2(acc0, wp[0][2*q+1], hv.y, acc0);
            FMA2(acc1, wp[1][2*q+1], hv.y, acc1);
            FMA2(acc2, wp[2][2*q+1], hv.y, acc2);
            FMA2(acc3, wp[3][2*q+1], hv.y, acc3);
        }
        float lo, hi, sum0, sum1, sum2, sum3;
        asm("mov.b64 {%0,%1}, %2;" : "=f"(lo), "=f"(hi) : "l"(acc0)); sum0 = lo + hi;
        asm("mov.b64 {%0,%1}, %2;" : "=f"(lo), "=f"(hi) : "l"(acc1)); sum1 = lo + hi;
        asm("mov.b64 {%0,%1}, %2;" : "=f"(lo), "=f"(hi) : "l"(acc2)); sum2 = lo + hi;
        asm("mov.b64 {%0,%1}, %2;" : "=f"(lo), "=f"(hi) : "l"(acc3)); sum3 = lo + hi;

        // reduce across the 8 segments (lanes stride 4)
#pragma unroll
        for (int m = 4; m <= 16; m <<= 1) {
            sum0 += __shfl_xor_sync(0xffffffffu, sum0, m);
            sum1 += __shfl_xor_sync(0xffffffffu, sum1, m);
            sum2 += __shfl_xor_sync(0xffffffffu, sum2, m);
            sum3 += __shfl_xor_sync(0xffffffffu, sum3, m);
        }

        if (writer) {
            const float h0 = tanhf(wx_c.x + sum0);
            const float h1 = tanhf(wx_c.y + sum1);
            const float h2 = tanhf(wx_c.z + sum2);
            const float h3 = tanhf(wx_c.w + sum3);
            *(float4*)&y_p[(size_t)t * DD + eg] =
                make_float4(h0 * gt_c.x, h1 * gt_c.y, h2 * gt_c.z, h3 * gt_c.w);
            *(float4*)&h_s[wbuf][eg] = make_float4(h0, h1, h2, h3);

            const uint32_t pa = h_peer + (uint32_t)(wbuf * DD + eg) * 4u;
            asm volatile("st.shared::cluster.f32 [%0], %1;" :: "r"(pa),      "f"(h0) : "memory");
            asm volatile("st.shared::cluster.f32 [%0], %1;" :: "r"(pa + 4),  "f"(h1) : "memory");
            asm volatile("st.shared::cluster.f32 [%0], %1;" :: "r"(pa + 8),  "f"(h2) : "memory");
            asm volatile("st.shared::cluster.f32 [%0], %1;" :: "r"(pa + 12), "f"(h3) : "memory");
            asm volatile("mbarrier.arrive.release.cluster.shared::cluster.b64 _, [%0];"
                         :: "r"(mbar_peer) : "memory");
            wx_c = wx_n; gt_c = gt_n;
        }

        // local arrive + wait (acquire cluster so peer's pushed h is visible)
        asm volatile("mbarrier.arrive.release.cluster.shared::cta.b64 _, [%0];"
                     :: "r"(mbar_a) : "memory");
        const uint32_t par = (uint32_t)(t & 1);
        uint32_t done;
        do {
            asm volatile(
                "{\n\t.reg .pred p;\n\t"
                "mbarrier.try_wait.parity.acquire.cluster.shared::cta.b64 p, [%1], %2;\n\t"
                "selp.b32 %0, 1, 0, p;\n\t}"
                : "=r"(done) : "r"(mbar_a), "r"(par) : "memory");
        } while (!done);

        rbuf = wbuf;
    }

    // don't exit while peer stores may target our smem
    asm volatile("barrier.cluster.arrive.aligned;" ::: "memory");
    asm volatile("barrier.cluster.wait.aligned;"   ::: "memory");
}

// ---------------------------------------------------------------------------
// Kernel 3: tied head  out[m][v] = sum_d ys[m][d] * E[v][d]  (unchanged)
// ---------------------------------------------------------------------------
__global__ __launch_bounds__(256) void head_kernel(
    const float* __restrict__ E, float* __restrict__ out)
{
    __shared__ float As[BK][BM + 4];
    __shared__ float Bs[BK][BN + 4];

    const int tid = threadIdx.x;
    const int m0  = blockIdx.x * BM;
    const int n0  = blockIdx.y * BN;

    const int lrow = tid >> 3;
    const int lk4  = tid & 7;
    const int tr = (tid >> 4) << 2;
    const int tc = (tid & 15) << 2;

    float acc[4][4];
#pragma unroll
    for (int i = 0; i < 4; i++)
#pragma unroll
        for (int j = 0; j < 4; j++) acc[i][j] = 0.f;

    for (int k0 = 0; k0 < DD; k0 += BK) {
        float4 va0 = *(const float4*)&g_ys[(size_t)(m0 + lrow)      * DD + k0 + lk4 * 4];
        float4 va1 = *(const float4*)&g_ys[(size_t)(m0 + lrow + 32) * DD + k0 + lk4 * 4];
        float4 vb0 = *(const float4*)&E  [(n0 + lrow)      * DD + k0 + lk4 * 4];
        float4 vb1 = *(const float4*)&E  [(n0 + lrow + 32) * DD + k0 + lk4 * 4];

        __syncthreads();

        As[lk4*4+0][lrow]      = va0.x; As[lk4*4+1][lrow]      = va0.y;
        As[lk4*4+2][lrow]      = va0.z; As[lk4*4+3][lrow]      = va0.w;
        As[lk4*4+0][lrow + 32] = va1.x; As[lk4*4+1][lrow + 32] = va1.y;
        As[lk4*4+2][lrow + 32] = va1.z; As[lk4*4+3][lrow + 32] = va1.w;

        Bs[lk4*4+0][lrow]      = vb0.x; Bs[lk4*4+1][lrow]      = vb0.y;
        Bs[lk4*4+2][lrow]      = vb0.z; Bs[lk4*4+3][lrow]      = vb0.w;
        Bs[lk4*4+0][lrow + 32] = vb1.x; Bs[lk4*4+1][lrow + 32] = vb1.y;
        Bs[lk4*4+2][lrow + 32] = vb1.z; Bs[lk4*4+3][lrow + 32] = vb1.w;

        __syncthreads();

#pragma unroll
        for (int kk = 0; kk < BK; kk++) {
            float4 a  = *(const float4*)&As[kk][tr];
            float4 bv = *(const float4*)&Bs[kk][tc];
            const float av[4] = {a.x, a.y, a.z, a.w};
            const float bb[4] = {bv.x, bv.y, bv.z, bv.w};
#pragma unroll
            for (int i = 0; i < 4; i++)
#pragma unroll
                for (int j = 0; j < 4; j++)
                    acc[i][j] = fmaf(av[i], bb[j], acc[i][j]);
        }
    }

#pragma unroll
    for (int i = 0; i < 4; i++) {
        float4 o = make_float4(acc[i][0], acc[i][1], acc[i][2], acc[i][3]);
        *(float4*)&out[(size_t)(m0 + tr + i) * DD + n0 + tc] = o;
    }
}

// ---------------------------------------------------------------------------
extern "C" void kernel_launch(void* const* d_in, const int* in_sizes, int n_in,
                              void* d_out, int out_size)
{
    const int*   tokens = (const int*)  d_in[0];
    const float* E      = (const float*)d_in[1];
    const float* Wx     = (const float*)d_in[2];
    const float* Wh     = (const float*)d_in[3];
    const float* Wz     = (const float*)d_in[4];
    float* out = (float*)d_out;

    dim3 gg(TOK_N / BM, DD / BN);
    proj_kernel<<<gg, 256>>>(tokens, E, Wx, Wz);
    rnn_kernel<<<128, 256>>>(Wh);
    head_kernel<<<gg, 256>>>(E, out);
}